// round 7
// baseline (speedup 1.0000x reference)
#include <cuda_runtime.h>
#include <cstdint>

// Problem constants
#define B_TOT  2048
#define S_LEN  256
#define DIN    3
#define HID    128
#define D_OUT  6
#define DT_F   0.1f

// 14 batch rows per CTA, 147 CTAs (one wave), 256 threads (1 CTA/SM, 256 regs/thr).
// Thread layout: np = tid&15 (neuron OCT n0=8np..8np+7), rsub = (tid>>4)&1
// (row half: 7 rows), ks = tid>>5 (K-slice: 16 cols). Warps uniform in ks
// -> all h loads are warp-uniform broadcasts.
// h stored SPLATTED: hsp[row][2j]=hsp[row][2j+1]=h[j]; LDS.128 -> (hj,hj,hj+1,hj+1)
// feeds neuron-packed f32x2 FMAs (each broadcast load feeds 8 FFMA2).
#define ROWS   14
#define RPG    7
#define NCTA   ((B_TOT + ROWS - 1) / ROWS)   // 147
#define NTHR   256
#define NSL    8                             // K slices
#define CPS    16                            // cols per slice
#define SPC    (2 * HID)                     // splat row pitch: 256 floats

#define XSZ    (ROWS * S_LEN * DIN)          // 10752 floats
#define HSPSZ  (ROWS * SPC)                  // 3584 floats per buffer
#define PARTSZ (NSL * ROWS * HID)            // 14336 floats
#define SMEMF  (XSZ + 2 * HSPSZ + PARTSZ)    // 32256 floats = 129024 B

typedef unsigned long long u64;

// ---- packed f32x2 ops ----
__device__ __forceinline__ u64 fma2(u64 a, u64 b, u64 c) {
    u64 d;
    asm("fma.rn.f32x2 %0, %1, %2, %3;" : "=l"(d) : "l"(a), "l"(b), "l"(c));
    return d;
}
__device__ __forceinline__ u64 add2(u64 a, u64 b) {
    u64 d;
    asm("add.rn.f32x2 %0, %1, %2;" : "=l"(d) : "l"(a), "l"(b));
    return d;
}
__device__ __forceinline__ u64 pk(float lo, float hi) {
    u64 v;
    asm("mov.b64 %0, {%1, %2};" : "=l"(v) : "f"(lo), "f"(hi));
    return v;
}
__device__ __forceinline__ void upk(u64 v, float& lo, float& hi) {
    asm("mov.b64 {%0, %1}, %2;" : "=f"(lo), "=f"(hi) : "l"(v));
}

// Accurate-enough tanh: ex2.approx + fast divide; abs err ~1e-6.
__device__ __forceinline__ float fast_tanh(float x) {
    float ax = fminf(fabsf(x), 15.0f);
    float e  = __expf(2.0f * ax);
    float t  = 1.0f - __fdividef(2.0f, e + 1.0f);
    return copysignf(t, x);
}

// softplus(x) = max(x,0) + log1p(exp(-|x|))  (stable, accurate)
__device__ __forceinline__ float softplus_acc(float x) {
    return fmaxf(x, 0.0f) + log1pf(__expf(-fabsf(x)));
}

extern __shared__ float smem_dyn[];

__global__ void __launch_bounds__(NTHR, 1)
cfc_kernel(const float* __restrict__ x,        // [B, S, 3]
           const float* __restrict__ W_xh,     // [128, 3]
           const float* __restrict__ W_hh,     // [128, 128]
           const float* __restrict__ b_hh,     // [128]
           const float* __restrict__ log_tau,  // [128]
           const float* __restrict__ fc_W,     // [6, 128]
           const float* __restrict__ fc_b,     // [6]
           float* __restrict__ out)            // [B, 6]
{
    float* xsh  = smem_dyn;            // x tile
    float* hsp0 = xsh + XSZ;           // splatted h, buffer 0
    float* hsp1 = hsp0 + HSPSZ;        // splatted h, buffer 1
    float* part = hsp1 + HSPSZ;        // partials [ks][row][neuron]

    const int tid  = threadIdx.x;
    const int np   = tid & 15;            // neuron oct: n0 = 8np .. 8np+7
    const int rsub = (tid >> 4) & 1;      // row half
    const int ks   = tid >> 5;            // K slice: cols [ks*16, ks*16+16)
    const int n0   = 8 * np;
    const int colb = ks * CPS;
    const int rowb = rsub * RPG;
    const int cb   = blockIdx.x * ROWS;   // global batch-row base

    // ---- W_hh: 4 neuron-pairs x 16 cols -> 64 u64 = 128 regs ----
    u64 W0[CPS], W1[CPS], W2[CPS], W3[CPS];
    {
        #pragma unroll
        for (int c = 0; c < CPS; c++) {
            W0[c] = pk(W_hh[(n0 + 0) * HID + colb + c], W_hh[(n0 + 1) * HID + colb + c]);
            W1[c] = pk(W_hh[(n0 + 2) * HID + colb + c], W_hh[(n0 + 3) * HID + colb + c]);
            W2[c] = pk(W_hh[(n0 + 4) * HID + colb + c], W_hh[(n0 + 5) * HID + colb + c]);
            W3[c] = pk(W_hh[(n0 + 6) * HID + colb + c], W_hh[(n0 + 7) * HID + colb + c]);
        }
    }

    const bool fin = (ks < RPG);          // this thread finishes one row
    const int  frow = rowb + ks;          // row it finishes (if fin)

    // finisher-only state: leak coefficients + persistent h (avoids re-reads)
    float aa[8], ho[8];
    #pragma unroll
    for (int i = 0; i < 8; i++) {
        aa[i] = fin ? (DT_F / (softplus_acc(log_tau[n0 + i]) + 0.001f)) : 0.0f;
        ho[i] = 0.0f;
    }

    // ---- stage x tile; zero splat-h buffers ----
    {
        const float* src = x + (size_t)cb * (S_LEN * DIN);
        int lim = (B_TOT - cb) * (S_LEN * DIN);
        if (lim > XSZ) lim = XSZ;
        for (int i = tid; i < XSZ; i += NTHR)
            xsh[i] = (i < lim) ? src[i] : 0.0f;
    }
    for (int i = tid; i < 2 * HSPSZ; i += NTHR) hsp0[i] = 0.0f;
    __syncthreads();

    // ================= sequential scan over S =================
    for (int s = 0; s < S_LEN; s++) {
        const float* hcur = (s & 1) ? hsp1 : hsp0;
        float*       hnxt = (s & 1) ? hsp0 : hsp1;

        // ---- matvec partials: 8 neurons x 7 rows over 16 cols ----
        u64 a0[RPG], a1[RPG], a2[RPG], a3[RPG];
        #pragma unroll
        for (int r = 0; r < RPG; r++) { a0[r] = 0; a1[r] = 0; a2[r] = 0; a3[r] = 0; }

        const float* hb = hcur + rowb * SPC + colb * 2;
        #pragma unroll
        for (int c2 = 0; c2 < CPS / 2; c2++) {     // 2 cols per iter
            #pragma unroll
            for (int r = 0; r < RPG; r++) {
                ulonglong2 hv = *reinterpret_cast<const ulonglong2*>(hb + r * SPC + c2 * 4);
                a0[r] = fma2(W0[2 * c2],     hv.x, a0[r]);
                a1[r] = fma2(W1[2 * c2],     hv.x, a1[r]);
                a2[r] = fma2(W2[2 * c2],     hv.x, a2[r]);
                a3[r] = fma2(W3[2 * c2],     hv.x, a3[r]);
                a0[r] = fma2(W0[2 * c2 + 1], hv.y, a0[r]);
                a1[r] = fma2(W1[2 * c2 + 1], hv.y, a1[r]);
                a2[r] = fma2(W2[2 * c2 + 1], hv.y, a2[r]);
                a3[r] = fma2(W3[2 * c2 + 1], hv.y, a3[r]);
            }
        }

        // ---- publish partials (skip own finish row: kept in regs) ----
        #pragma unroll
        for (int r = 0; r < RPG; r++) {
            if (fin && r == ks) continue;         // finisher keeps its own slice
            float* p = part + (ks * ROWS + rowb + r) * HID + n0;
            ulonglong2 v1; v1.x = a0[r]; v1.y = a1[r];
            ulonglong2 v2; v2.x = a2[r]; v2.y = a3[r];
            *reinterpret_cast<ulonglong2*>(p)     = v1;
            *reinterpret_cast<ulonglong2*>(p + 4) = v2;
        }
        __syncthreads();

        // ---- finish: combine 8 slices, x-proj, tanh, leaky update ----
        if (fin) {
            u64 z0 = a0[ks], z1 = a1[ks], z2 = a2[ks], z3 = a3[ks];
            #pragma unroll
            for (int q = 0; q < NSL; q++) {
                if (q == ks) continue;
                const float* p = part + (q * ROWS + frow) * HID + n0;
                ulonglong2 v1 = *reinterpret_cast<const ulonglong2*>(p);
                ulonglong2 v2 = *reinterpret_cast<const ulonglong2*>(p + 4);
                z0 = add2(z0, v1.x);
                z1 = add2(z1, v1.y);
                z2 = add2(z2, v2.x);
                z3 = add2(z3, v2.y);
            }
            float z[8];
            upk(z0, z[0], z[1]);
            upk(z1, z[2], z[3]);
            upk(z2, z[4], z[5]);
            upk(z3, z[6], z[7]);

            // x projection params (L1-hot after step 0)
            float wv[24];
            {
                const float4* wp4 = reinterpret_cast<const float4*>(W_xh + 24 * np);
                #pragma unroll
                for (int k = 0; k < 6; k++) {
                    float4 q4 = wp4[k];
                    wv[4 * k + 0] = q4.x; wv[4 * k + 1] = q4.y;
                    wv[4 * k + 2] = q4.z; wv[4 * k + 3] = q4.w;
                }
            }
            float bv[8];
            {
                float4 ba = reinterpret_cast<const float4*>(b_hh)[2 * np];
                float4 bb = reinterpret_cast<const float4*>(b_hh)[2 * np + 1];
                bv[0] = ba.x; bv[1] = ba.y; bv[2] = ba.z; bv[3] = ba.w;
                bv[4] = bb.x; bv[5] = bb.y; bv[6] = bb.z; bv[7] = bb.w;
            }
            const float* xr = xsh + frow * (S_LEN * DIN) + s * 3;
            float x0 = xr[0], x1 = xr[1], x2 = xr[2];

            float* hd = hnxt + frow * SPC + 16 * np;
            u64 sp[8];
            #pragma unroll
            for (int i = 0; i < 8; i++) {
                float zi = z[i] + fmaf(wv[3 * i], x0,
                              fmaf(wv[3 * i + 1], x1,
                              fmaf(wv[3 * i + 2], x2, bv[i])));
                float f = fast_tanh(zi);
                ho[i] = fmaf(aa[i], f - ho[i], ho[i]);
                sp[i] = pk(ho[i], ho[i]);
            }
            ulonglong2 o;
            o.x = sp[0]; o.y = sp[1];
            *reinterpret_cast<ulonglong2*>(hd)      = o;
            o.x = sp[2]; o.y = sp[3];
            *reinterpret_cast<ulonglong2*>(hd + 4)  = o;
            o.x = sp[4]; o.y = sp[5];
            *reinterpret_cast<ulonglong2*>(hd + 8)  = o;
            o.x = sp[6]; o.y = sp[7];
            *reinterpret_cast<ulonglong2*>(hd + 12) = o;
        }
        __syncthreads();
    }

    // ================= output head: softplus(h_T @ fc_W^T + fc_b) =================
    const float* hf = hsp0;   // S_LEN even -> final state in buffer 0 (splatted)
    if (tid < ROWS * D_OUT) {
        const int r = tid / D_OUT;
        const int o = tid % D_OUT;
        const int grow = cb + r;
        if (grow < B_TOT) {
            float z = fc_b[o];
            const float* wrow = fc_W + o * HID;
            const float* hrow = hf + r * SPC;
            #pragma unroll
            for (int j = 0; j < HID; j++)
                z = fmaf(wrow[j], hrow[2 * j], z);
            out[grow * D_OUT + o] = softplus_acc(z);
        }
    }
}

extern "C" void kernel_launch(void* const* d_in, const int* in_sizes, int n_in,
                              void* d_out, int out_size) {
    const float* x       = (const float*)d_in[0];
    const float* W_xh    = (const float*)d_in[1];
    const float* W_hh    = (const float*)d_in[2];
    const float* b_hh    = (const float*)d_in[3];
    const float* log_tau = (const float*)d_in[4];
    const float* fc_W    = (const float*)d_in[5];
    const float* fc_b    = (const float*)d_in[6];
    float* out = (float*)d_out;

    const size_t shmem = (size_t)SMEMF * sizeof(float);  // 129024 B
    cudaFuncSetAttribute(cfc_kernel, cudaFuncAttributeMaxDynamicSharedMemorySize, (int)shmem);

    cfc_kernel<<<NCTA, NTHR, shmem>>>(x, W_xh, W_hh, b_hh, log_tau, fc_W, fc_b, out);
}

// round 8
// speedup vs baseline: 1.2409x; 1.2409x over previous
#include <cuda_runtime.h>
#include <cstdint>

// Problem constants
#define B_TOT  2048
#define S_LEN  256
#define DIN    3
#define HID    128
#define D_OUT  6
#define DT_F   0.1f

// 14 rows/CTA, 147 CTAs, 256 threads (8 warps), 1 CTA/SM.
// Warp w: neuron block nblk=w&3 (neurons 32nblk..+31), rows rowbase=(w>>2)*7 ..+6.
// Lane: np=lane&7 (neurons n0=32nblk+4np..+3), ks=lane>>3 (K-slice cols ks*32..+31).
// K-reduction intra-warp via shfl_xor(8,16); finish split by neuron (lane finishes
// neuron n0+ks for all 7 rows, old-h in registers). ONE barrier per step.
// h stored splatted+skewed: row pitch 272 floats, slice q at offset q*68
// (68*4B mod 128B = 16B -> the 4 ks slices hit distinct banks).
#define ROWS   14
#define NCTA   ((B_TOT + ROWS - 1) / ROWS)   // 147
#define NTHR   256
#define SLICE  68                            // floats per k-slice (64 data + 4 skew)
#define SPC    (4 * SLICE)                   // 272 floats per row

#define XSZ    (ROWS * S_LEN * DIN)          // 10752 floats
#define HSPSZ  (ROWS * SPC)                  // 3808 floats per buffer
#define SMEMF  (XSZ + 2 * HSPSZ)             // 18368 floats = 73472 B

typedef unsigned long long u64;

// ---- packed f32x2 ops ----
__device__ __forceinline__ u64 fma2(u64 a, u64 b, u64 c) {
    u64 d;
    asm("fma.rn.f32x2 %0, %1, %2, %3;" : "=l"(d) : "l"(a), "l"(b), "l"(c));
    return d;
}
__device__ __forceinline__ u64 add2(u64 a, u64 b) {
    u64 d;
    asm("add.rn.f32x2 %0, %1, %2;" : "=l"(d) : "l"(a), "l"(b));
    return d;
}
__device__ __forceinline__ u64 pk(float lo, float hi) {
    u64 v;
    asm("mov.b64 %0, {%1, %2};" : "=l"(v) : "f"(lo), "f"(hi));
    return v;
}
__device__ __forceinline__ void upk(u64 v, float& lo, float& hi) {
    asm("mov.b64 {%0, %1}, %2;" : "=f"(lo), "=f"(hi) : "l"(v));
}

// Accurate-enough tanh: ex2.approx + fast divide; abs err ~1e-6.
__device__ __forceinline__ float fast_tanh(float x) {
    float ax = fminf(fabsf(x), 15.0f);
    float e  = __expf(2.0f * ax);
    float t  = 1.0f - __fdividef(2.0f, e + 1.0f);
    return copysignf(t, x);
}

// softplus(x) = max(x,0) + log1p(exp(-|x|))  (stable, accurate)
__device__ __forceinline__ float softplus_acc(float x) {
    return fmaxf(x, 0.0f) + log1pf(__expf(-fabsf(x)));
}

extern __shared__ float smem_dyn[];

__global__ void __launch_bounds__(NTHR, 1)
cfc_kernel(const float* __restrict__ x,        // [B, S, 3]
           const float* __restrict__ W_xh,     // [128, 3]
           const float* __restrict__ W_hh,     // [128, 128]
           const float* __restrict__ b_hh,     // [128]
           const float* __restrict__ log_tau,  // [128]
           const float* __restrict__ fc_W,     // [6, 128]
           const float* __restrict__ fc_b,     // [6]
           float* __restrict__ out)            // [B, 6]
{
    float* xsh  = smem_dyn;            // x tile
    float* hsp0 = xsh + XSZ;           // splatted+skewed h, buffer 0
    float* hsp1 = hsp0 + HSPSZ;        // splatted+skewed h, buffer 1

    const int tid  = threadIdx.x;
    const int lane = tid & 31;
    const int w    = tid >> 5;
    const int np   = lane & 7;            // 4-neuron group within block
    const int ks   = lane >> 3;           // K-slice 0..3
    const int nblk = w & 3;               // neuron block (32 neurons)
    const int rowbase = (w >> 2) * 7;     // 0 or 7
    const int n0   = 32 * nblk + 4 * np;  // first neuron of this lane's quad
    const int colb = ks * 32;             // K columns [colb, colb+32)
    const int cb   = blockIdx.x * ROWS;   // global batch-row base

    // ---- W_hh: 2 neuron-pairs x 32 cols -> 64 u64 = 128 regs ----
    u64 W01[32], W23[32];
    #pragma unroll
    for (int c = 0; c < 32; c++) {
        W01[c] = pk(W_hh[(n0 + 0) * HID + colb + c], W_hh[(n0 + 1) * HID + colb + c]);
        W23[c] = pk(W_hh[(n0 + 2) * HID + colb + c], W_hh[(n0 + 3) * HID + colb + c]);
    }

    // ---- finish params for THIS lane's finish neuron nf = n0 + ks ----
    const int nf = n0 + ks;
    const float wxf0 = W_xh[nf * 3 + 0];
    const float wxf1 = W_xh[nf * 3 + 1];
    const float wxf2 = W_xh[nf * 3 + 2];
    const float bbf  = b_hh[nf];
    const float aaf  = DT_F / (softplus_acc(log_tau[nf]) + 0.001f);
    float ho[7];                          // old h for (rows, nf), in registers
    #pragma unroll
    for (int r = 0; r < 7; r++) ho[r] = 0.0f;

    // ---- stage x tile; zero h buffers ----
    {
        const float* src = x + (size_t)cb * (S_LEN * DIN);
        int lim = (B_TOT - cb) * (S_LEN * DIN);
        if (lim > XSZ) lim = XSZ;
        for (int i = tid; i < XSZ; i += NTHR)
            xsh[i] = (i < lim) ? src[i] : 0.0f;
    }
    for (int i = tid; i < 2 * HSPSZ; i += NTHR) hsp0[i] = 0.0f;
    __syncthreads();

    // ================= sequential scan over S =================
    for (int s = 0; s < S_LEN; s++) {
        const float* hcur = (s & 1) ? hsp1 : hsp0;
        float*       hnxt = (s & 1) ? hsp0 : hsp1;

        // ---- matvec partials: this lane's 4 neurons x 7 rows x 32 cols ----
        u64 zA[7], zB[7];
        #pragma unroll
        for (int r = 0; r < 7; r++) { zA[r] = 0ull; zB[r] = 0ull; }

        const float* hb = hcur + rowbase * SPC + ks * SLICE;
        #pragma unroll
        for (int c2 = 0; c2 < 16; c2++) {       // 2 splatted cols per iter
            #pragma unroll
            for (int r = 0; r < 7; r++) {
                ulonglong2 hv = *reinterpret_cast<const ulonglong2*>(
                    hb + r * SPC + c2 * 4);     // (hj,hj,hj+1,hj+1)
                zA[r] = fma2(W01[2 * c2],     hv.x, zA[r]);
                zB[r] = fma2(W23[2 * c2],     hv.x, zB[r]);
                zA[r] = fma2(W01[2 * c2 + 1], hv.y, zA[r]);
                zB[r] = fma2(W23[2 * c2 + 1], hv.y, zB[r]);
            }
        }

        // ---- intra-warp K-reduction: sum over the 4 ks slices ----
        #pragma unroll
        for (int r = 0; r < 7; r++) {
            zA[r] = add2(zA[r], __shfl_xor_sync(0xffffffffu, zA[r], 8));
            zA[r] = add2(zA[r], __shfl_xor_sync(0xffffffffu, zA[r], 16));
            zB[r] = add2(zB[r], __shfl_xor_sync(0xffffffffu, zB[r], 8));
            zB[r] = add2(zB[r], __shfl_xor_sync(0xffffffffu, zB[r], 16));
        }

        // ---- finish: every lane finishes neuron nf for all 7 rows ----
        #pragma unroll
        for (int r = 0; r < 7; r++) {
            float z0, z1, z2, z3;
            upk(zA[r], z0, z1);
            upk(zB[r], z2, z3);
            float zf = (ks == 0) ? z0 : (ks == 1) ? z1 : (ks == 2) ? z2 : z3;
            const float* xr = xsh + (rowbase + r) * (S_LEN * DIN) + s * 3;
            zf += fmaf(wxf0, xr[0], fmaf(wxf1, xr[1], fmaf(wxf2, xr[2], bbf)));
            float f = fast_tanh(zf);
            ho[r] = fmaf(aaf, f - ho[r], ho[r]);
            // splat-store new h (skewed layout): neuron nf -> slice nblk,
            // within-slice index (4np+ks)*2
            *reinterpret_cast<u64*>(hnxt + (rowbase + r) * SPC + nblk * SLICE
                                    + 8 * np + 2 * ks) = pk(ho[r], ho[r]);
        }
        __syncthreads();   // the ONLY barrier per step
    }

    // ================= output head: softplus(h_T @ fc_W^T + fc_b) =================
    const float* hf = hsp0;   // S_LEN even -> final state in buffer 0
    if (tid < ROWS * D_OUT) {
        const int r = tid / D_OUT;
        const int o = tid % D_OUT;
        const int grow = cb + r;
        if (grow < B_TOT) {
            float z = fc_b[o];
            const float* wrow = fc_W + o * HID;
            const float* hrow = hf + r * SPC;
            #pragma unroll
            for (int j = 0; j < HID; j++)
                z = fmaf(wrow[j], hrow[(j >> 5) * SLICE + (j & 31) * 2], z);
            out[grow * D_OUT + o] = softplus_acc(z);
        }
    }
}

extern "C" void kernel_launch(void* const* d_in, const int* in_sizes, int n_in,
                              void* d_out, int out_size) {
    const float* x       = (const float*)d_in[0];
    const float* W_xh    = (const float*)d_in[1];
    const float* W_hh    = (const float*)d_in[2];
    const float* b_hh    = (const float*)d_in[3];
    const float* log_tau = (const float*)d_in[4];
    const float* fc_W    = (const float*)d_in[5];
    const float* fc_b    = (const float*)d_in[6];
    float* out = (float*)d_out;

    const size_t shmem = (size_t)SMEMF * sizeof(float);  // 73472 B
    cudaFuncSetAttribute(cfc_kernel, cudaFuncAttributeMaxDynamicSharedMemorySize, (int)shmem);

    cfc_kernel<<<NCTA, NTHR, shmem>>>(x, W_xh, W_hh, b_hh, log_tau, fc_W, fc_b, out);
}